// round 10
// baseline (speedup 1.0000x reference)
#include <cuda_runtime.h>
#include <cuda_bf16.h>
#include <stdint.h>

// Problem constants
#define B_   4
#define N_   2048
#define NF_  512
#define H_   8
#define D_   64
#define W_   4
#define NW_  512          // N_/W_
#define KEEP_ 64
#define QKVN 1536         // 3*H*D
#define NROWS (B_*H_*NW_) // 16384
#define BHND (B_*H_*N_*D_)

// SIMT GEMM tiling
#define BM 128
#define BN 128
#define BK 16

// hetero kernel block-role ranges
#define GEMM_BLOCKS 768          // (QKVN/BN=12) x ((B_*N_)/BM=64)
#define PB_BLOCKS   256
#define HET_BLOCKS  (GEMM_BLOCKS + PB_BLOCKS + NROWS)

// ---------------- device scratch (no allocations allowed) ----------------
__device__ float g_q[BHND];
__device__ float g_k[BHND];
__device__ float g_v[BHND];
__device__ float g_tab[(2*N_-1)*H_];      // 4095 x 8
__device__ int   g_idx[NROWS*KEEP_];      // 16384 x 64
__device__ float g_attn[B_*N_*H_*D_];     // (B, N, H*D)

// ---------------- threefry2x32 (JAX-compatible, key=(0,1)) ----------------
__device__ __forceinline__ uint32_t rotl32(uint32_t x, int r){ return (x<<r) | (x>>(32-r)); }

__device__ __forceinline__ void threefry_0_1(uint32_t c0, uint32_t c1, uint32_t& o0, uint32_t& o1){
    const uint32_t ks0 = 0u, ks1 = 1u, ks2 = 0x1BD11BDBu;
    uint32_t x0 = c0 + ks0;
    uint32_t x1 = c1 + ks1;
#define QR(r) { x0 += x1; x1 = rotl32(x1, r); x1 ^= x0; }
    QR(13) QR(15) QR(26) QR(6)   x0 += ks1; x1 += ks2 + 1u;
    QR(17) QR(29) QR(16) QR(24)  x0 += ks2; x1 += ks0 + 2u;
    QR(13) QR(15) QR(26) QR(6)   x0 += ks0; x1 += ks1 + 3u;
    QR(17) QR(29) QR(16) QR(24)  x0 += ks1; x1 += ks2 + 4u;
    QR(13) QR(15) QR(26) QR(6)   x0 += ks2; x1 += ks0 + 5u;
#undef QR
    o0 = x0; o1 = x1;
}

// ---------------- fast block exclusive scan (256 threads) ----------------
__device__ __forceinline__ int block_scan_excl(int val, int tid, int* scratch){
    int lane = tid & 31, wid = tid >> 5;
    int x = val;
#pragma unroll
    for (int o=1; o<32; o<<=1){
        int t = __shfl_up_sync(0xffffffffu, x, o);
        if (lane >= o) x += t;
    }
    if (lane == 31) scratch[wid] = x;
    __syncthreads();
    if (wid == 0 && lane < 8){
        int y = scratch[lane];
#pragma unroll
        for (int o=1; o<8; o<<=1){
            int t = __shfl_up_sync(0xFFu, y, o);
            if (lane >= o) y += t;
        }
        scratch[lane] = y;
    }
    __syncthreads();
    int base = (wid == 0) ? 0 : scratch[wid-1];
    return base + x - val;
}

// ---------------- heterogeneous kernel: QKV GEMM (768) | pb MLP (256) | topk (16384) ----------------
// All three roles are mutually independent; GEMM blocks (long pole) schedule first,
// ALU-bound topk + pb backfill SMs as GEMM blocks retire.
// smem union: gemm As|Bs = 8192 floats; pb h0 = 8192 floats; topk hist+scratch = 264 ints.
#define AS(b,k,m) sbuf[(b)*2048 + (k)*128 + (m)]
#define BS(b,k,n) sbuf[4096 + (b)*2048 + (k)*128 + (n)]

__global__ __launch_bounds__(256) void hetero_kernel(
    const float* __restrict__ A,  const float* __restrict__ Bm, const float* __restrict__ bias,
    const float* __restrict__ w0, const float* __restrict__ b0,
    const float* __restrict__ w1, const float* __restrict__ b1,
    const float* __restrict__ w2, const float* __restrict__ b2)
{
    __shared__ float sbuf[8192];
    const int bid = blockIdx.x;
    const int tid = threadIdx.x;

    if (bid < GEMM_BLOCKS){
        // ======== QKV GEMM role (code path identical to R9's qkv_gemm_kernel) ========
        const int bx = bid % (QKVN/BN), by = bid / (QKVN/BN);
        const int row0 = by*BM, col0 = bx*BN;

        const int ar = tid>>2;
        const int ac = (tid&3)*4;
        const int br = tid>>5;
        const int bc = (tid&31)*4;

        const int wid = tid>>5, lane = tid&31;
        const int m0 = (wid&3)*32 + (lane&3)*8;
        const int n0 = (wid>>2)*64 + (lane>>2)*8;

        float acc[8][8];
#pragma unroll
        for (int i=0;i<8;i++)
#pragma unroll
            for (int j=0;j<8;j++) acc[i][j]=0.f;

        float4 pa0, pa1, pb0, pb1;
        pa0 = *(const float4*)&A[(row0+ar)*NF_ + ac];
        pa1 = *(const float4*)&A[(row0+ar+64)*NF_ + ac];
        pb0 = *(const float4*)&Bm[br*QKVN + col0+bc];
        pb1 = *(const float4*)&Bm[(br+8)*QKVN + col0+bc];
        AS(0,ac+0,ar) = pa0.x; AS(0,ac+1,ar) = pa0.y; AS(0,ac+2,ar) = pa0.z; AS(0,ac+3,ar) = pa0.w;
        AS(0,ac+0,ar+64) = pa1.x; AS(0,ac+1,ar+64) = pa1.y; AS(0,ac+2,ar+64) = pa1.z; AS(0,ac+3,ar+64) = pa1.w;
        *(float4*)&BS(0,br,bc) = pb0;
        *(float4*)&BS(0,br+8,bc) = pb1;
        __syncthreads();

        int buf = 0;
        const int NT = NF_/BK;
        for (int t=0; t<NT; t++){
            const int k0n = (t+1)*BK;
            if (t+1 < NT){
                pa0 = *(const float4*)&A[(row0+ar)*NF_ + k0n+ac];
                pa1 = *(const float4*)&A[(row0+ar+64)*NF_ + k0n+ac];
                pb0 = *(const float4*)&Bm[(k0n+br)*QKVN + col0+bc];
                pb1 = *(const float4*)&Bm[(k0n+br+8)*QKVN + col0+bc];
            }
#pragma unroll
            for (int kk=0; kk<BK; kk++){
                float4 a0 = *(const float4*)&AS(buf,kk,m0);
                float4 a1 = *(const float4*)&AS(buf,kk,m0+4);
                float4 b0v = *(const float4*)&BS(buf,kk,n0);
                float4 b1v = *(const float4*)&BS(buf,kk,n0+4);
                float av[8] = {a0.x,a0.y,a0.z,a0.w,a1.x,a1.y,a1.z,a1.w};
                float bv[8] = {b0v.x,b0v.y,b0v.z,b0v.w,b1v.x,b1v.y,b1v.z,b1v.w};
#pragma unroll
                for (int i=0;i<8;i++)
#pragma unroll
                    for (int j=0;j<8;j++) acc[i][j] += av[i]*bv[j];
            }
            if (t+1 < NT){
                const int nb = buf^1;
                AS(nb,ac+0,ar) = pa0.x; AS(nb,ac+1,ar) = pa0.y; AS(nb,ac+2,ar) = pa0.z; AS(nb,ac+3,ar) = pa0.w;
                AS(nb,ac+0,ar+64) = pa1.x; AS(nb,ac+1,ar+64) = pa1.y; AS(nb,ac+2,ar+64) = pa1.z; AS(nb,ac+3,ar+64) = pa1.w;
                *(float4*)&BS(nb,br,bc) = pb0;
                *(float4*)&BS(nb,br+8,bc) = pb1;
                __syncthreads();
                buf = nb;
            }
        }

        float bj[8];
#pragma unroll
        for (int j=0;j<8;j++) bj[j] = bias[col0+n0+j];
#pragma unroll
        for (int i=0;i<8;i++){
            int row = row0 + m0 + i;
            int b = row >> 11, n = row & 2047;
#pragma unroll
            for (int j=0;j<8;j++){
                int col = col0 + n0 + j;
                int h = col / 192;
                int rem = col - h*192;
                int d = rem / 3;
                int s = rem - d*3;
                float val = acc[i][j] + bj[j];
                long long off = ((long long)(b*H_ + h)*N_ + n)*D_ + d;
                if (s == 0) g_q[off] = val;
                else if (s == 1) g_k[off] = val;
                else g_v[off] = val;
            }
        }
    }
    else if (bid < GEMM_BLOCKS + PB_BLOCKS){
        // ======== position-bias MLP role ========
        float* h0 = sbuf;   // 8192 floats
        int r0 = (bid - GEMM_BLOCKS) * 16;

        for (int i = tid; i < 16*512; i += 256){
            int r = i >> 9, j = i & 511;
            int rr = r0 + r;
            float v = 0.f;
            if (rr < 2*N_-1){
                float pos = (float)(rr - (N_-1));
                float t = pos * w0[j] + b0[j];
                v = t / (1.f + expf(-t));
            }
            h0[r*512 + j] = v;
        }
        __syncthreads();

        float acc[2][16];
#pragma unroll
        for (int c=0;c<2;c++)
#pragma unroll
            for (int r=0;r<16;r++) acc[c][r]=0.f;

        for (int k=0;k<512;k++){
            float wA = w1[k*512 + tid];
            float wB = w1[k*512 + tid + 256];
#pragma unroll
            for (int r=0;r<16;r++){
                float hv = h0[r*512 + k];
                acc[0][r] += hv*wA;
                acc[1][r] += hv*wB;
            }
        }
        __syncthreads();

#pragma unroll
        for (int c=0;c<2;c++){
            int j = tid + c*256;
            float bb = b1[j];
#pragma unroll
            for (int r=0;r<16;r++){
                float t = acc[c][r] + bb;
                h0[r*512 + j] = t / (1.f + expf(-t));
            }
        }
        __syncthreads();

        int warp = tid >> 5, lane = tid & 31;
        for (int task = warp; task < 128; task += 8){
            int r = task >> 3, o = task & 7;
            float s = 0.f;
            for (int k = lane; k < 512; k += 32) s += h0[r*512 + k] * w2[k*8 + o];
#pragma unroll
            for (int off=16; off; off>>=1) s += __shfl_xor_sync(0xffffffffu, s, off);
            if (lane == 0){
                int rr = r0 + r;
                if (rr < 2*N_-1) g_tab[rr*8 + o] = s + b2[o];
            }
        }
    }
    else {
        // ======== top-k role (bit-identical selection math, verified R3/R9) ========
        int* hist    = (int*)sbuf;
        int* scratch = ((int*)sbuf) + 256;
        __shared__ unsigned s_prefix;
        __shared__ int s_target;

        int row = bid - (GEMM_BLOCKS + PB_BLOCKS);
        int w = row & (NW_-1);
        unsigned base = (unsigned)row * 2048u;

        unsigned kk[8];
#pragma unroll
        for (int q=0; q<8; q++){
            int n = tid*8 + q;
            unsigned i = base + (unsigned)n;
            unsigned o0, o1;
            threefry_0_1(0u, i, o0, o1);
            unsigned bits = o0 ^ o1;
            float u = __uint_as_float((bits >> 9) | 0x3F800000u) - 1.0f;
            float noise = 3.0f * expf(-0.5f * log1pf(-u));
            int jblk = n >> 2;
            int dd = w - jblk; if (dd < 0) dd = -dd;
            float score = (float)dd - noise;
            unsigned fb = __float_as_uint(score);
            kk[q] = (fb & 0x80000000u) ? ~fb : (fb | 0x80000000u);
        }

        unsigned prefix = 0, mask = 0;
        int target = KEEP_;
#pragma unroll 1
        for (int pass = 0; pass < 4; pass++){
            int shift = 24 - 8*pass;
            hist[tid] = 0;
            __syncthreads();
#pragma unroll
            for (int q=0; q<8; q++){
                if ((kk[q] & mask) == prefix) atomicAdd(&hist[(kk[q] >> shift) & 255u], 1);
            }
            __syncthreads();
            int hv = hist[tid];
            __syncthreads();
            int excl = block_scan_excl(hv, tid, scratch);
            int incl = excl + hv;
            if (excl < target && target <= incl){
                s_prefix = prefix | ((unsigned)tid << shift);
                s_target = target - excl;
            }
            __syncthreads();
            prefix = s_prefix; target = s_target;
            mask |= (0xFFu << shift);
        }
        unsigned T = prefix;
        int r = target;

        int eq_cnt = 0;
#pragma unroll
        for (int q=0;q<8;q++) eq_cnt += (kk[q] == T);
        int eq_off = block_scan_excl(eq_cnt, tid, scratch);

        unsigned chflag = 0; int ch_cnt = 0; int er = eq_off;
#pragma unroll
        for (int q=0;q<8;q++){
            unsigned k = kk[q];
            bool ch = false;
            if (k < T) ch = true;
            else if (k == T){ ch = (er < r); er++; }
            if (ch){ chflag |= (1u<<q); ch_cnt++; }
        }
        int pos = block_scan_excl(ch_cnt, tid, scratch);
#pragma unroll
        for (int q=0;q<8;q++){
            if (chflag & (1u<<q)){
                g_idx[row*KEEP_ + pos] = tid*8 + q;
                pos++;
            }
        }
    }
}

// ---------------- attention per (b,h,blk): 4 queries x 64 selected keys ----------------
__global__ __launch_bounds__(256) void attn_kernel()
{
    __shared__ float qs[4*64];
    __shared__ float ks[64*68];
    __shared__ float vs[64*68];
    __shared__ float sv[4*64];
    __shared__ float pm[4], psum[4];
    __shared__ int sidx[64];

    int row = blockIdx.x, tid = threadIdx.x;
    int w = row & (NW_-1);
    int bh = row >> 9;
    int h = bh & 7, b = bh >> 3;

    if (tid < 64) sidx[tid] = g_idx[row*KEEP_ + tid];
    __syncthreads();

    const float4* kb4 = (const float4*)(g_k + (long long)bh * N_ * D_);
    const float4* vb4 = (const float4*)(g_v + (long long)bh * N_ * D_);
    const float* qbase = g_q + ((long long)bh * N_ + w*W_) * D_;

    qs[tid] = qbase[tid];
    for (int i = tid; i < 64*16; i += 256){
        int z = i >> 4, d4 = i & 15;
        int key = sidx[z];
        *(float4*)&ks[z*68 + d4*4] = kb4[key*16 + d4];
        *(float4*)&vs[z*68 + d4*4] = vb4[key*16 + d4];
    }
    __syncthreads();

    int wi = tid >> 6, z = tid & 63;
    const float4* qs4 = (const float4*)qs;
    const float4* ks4 = (const float4*)ks;
    float acc = 0.f;
#pragma unroll
    for (int d4=0; d4<16; d4++){
        float4 qv = qs4[wi*16 + d4];
        float4 kv = ks4[z*17 + d4];
        acc += qv.x*kv.x + qv.y*kv.y + qv.z*kv.z + qv.w*kv.w;
    }
    int rel = (w*W_ + wi) - sidx[z] + (N_-1);
    float val = acc * 0.125f + g_tab[rel*8 + h];
    sv[tid] = val;
    __syncthreads();

    if (tid < 128){
        int wr = tid >> 5, lane = tid & 31;
        float v1 = sv[wr*64 + lane], v2 = sv[wr*64 + lane + 32];
        float m = fmaxf(v1, v2);
#pragma unroll
        for (int off=16; off; off>>=1) m = fmaxf(m, __shfl_xor_sync(0xffffffffu, m, off));
        float s = expf(v1 - m) + expf(v2 - m);
#pragma unroll
        for (int off=16; off; off>>=1) s += __shfl_xor_sync(0xffffffffu, s, off);
        if (lane == 0){ pm[wr] = m; psum[wr] = s; }
    }
    __syncthreads();

    float p = expf(val - pm[wi]) / psum[wi];
    sv[tid] = p;
    __syncthreads();

    int d = z;
    const float4* sv4 = (const float4*)sv;
    float o = 0.f;
#pragma unroll
    for (int z4=0; z4<16; z4++){
        float4 p4 = sv4[wi*16 + z4];
        o += p4.x*vs[(z4*4+0)*68 + d] + p4.y*vs[(z4*4+1)*68 + d]
           + p4.z*vs[(z4*4+2)*68 + d] + p4.w*vs[(z4*4+3)*68 + d];
    }
    g_attn[(((long long)b*N_ + w*W_ + wi)*H_ + h)*D_ + d] = o;
}

// ---------------- GEMM 2: output projection (128x128x16, 8x8 microtile) ----------------
__global__ __launch_bounds__(256) void out_gemm_kernel(const float* __restrict__ Bm,
                                                       const float* __restrict__ bias,
                                                       float* __restrict__ C)
{
    __shared__ float As[2][BK][BM];
    __shared__ float Bs[2][BK][BN];
    const int tid = threadIdx.x;
    const int row0 = blockIdx.y*BM, col0 = blockIdx.x*BN;

    const int ar = tid>>2;
    const int ac = (tid&3)*4;
    const int br = tid>>5;
    const int bc = (tid&31)*4;

    const int wid = tid>>5, lane = tid&31;
    const int m0 = (wid&3)*32 + (lane&3)*8;
    const int n0 = (wid>>2)*64 + (lane>>2)*8;

    float acc[8][8];
#pragma unroll
    for (int i=0;i<8;i++)
#pragma unroll
        for (int j=0;j<8;j++) acc[i][j]=0.f;

    float4 pa0, pa1, pb0, pb1;
    pa0 = *(const float4*)&g_attn[(row0+ar)*NF_ + ac];
    pa1 = *(const float4*)&g_attn[(row0+ar+64)*NF_ + ac];
    pb0 = *(const float4*)&Bm[br*NF_ + col0+bc];
    pb1 = *(const float4*)&Bm[(br+8)*NF_ + col0+bc];
    As[0][ac+0][ar] = pa0.x; As[0][ac+1][ar] = pa0.y; As[0][ac+2][ar] = pa0.z; As[0][ac+3][ar] = pa0.w;
    As[0][ac+0][ar+64] = pa1.x; As[0][ac+1][ar+64] = pa1.y; As[0][ac+2][ar+64] = pa1.z; As[0][ac+3][ar+64] = pa1.w;
    *(float4*)&Bs[0][br][bc] = pb0;
    *(float4*)&Bs[0][br+8][bc] = pb1;
    __syncthreads();

    int buf = 0;
    const int NT = NF_/BK;
    for (int t=0; t<NT; t++){
        const int k0n = (t+1)*BK;
        if (t+1 < NT){
            pa0 = *(const float4*)&g_attn[(row0+ar)*NF_ + k0n+ac];
            pa1 = *(const float4*)&g_attn[(row0+ar+64)*NF_ + k0n+ac];
            pb0 = *(const float4*)&Bm[(k0n+br)*NF_ + col0+bc];
            pb1 = *(const float4*)&Bm[(k0n+br+8)*NF_ + col0+bc];
        }
#pragma unroll
        for (int kk=0; kk<BK; kk++){
            float4 a0 = *(const float4*)&As[buf][kk][m0];
            float4 a1 = *(const float4*)&As[buf][kk][m0+4];
            float4 b0 = *(const float4*)&Bs[buf][kk][n0];
            float4 b1 = *(const float4*)&Bs[buf][kk][n0+4];
            float av[8] = {a0.x,a0.y,a0.z,a0.w,a1.x,a1.y,a1.z,a1.w};
            float bv[8] = {b0.x,b0.y,b0.z,b0.w,b1.x,b1.y,b1.z,b1.w};
#pragma unroll
            for (int i=0;i<8;i++)
#pragma unroll
                for (int j=0;j<8;j++) acc[i][j] += av[i]*bv[j];
        }
        if (t+1 < NT){
            const int nb = buf^1;
            As[nb][ac+0][ar] = pa0.x; As[nb][ac+1][ar] = pa0.y; As[nb][ac+2][ar] = pa0.z; As[nb][ac+3][ar] = pa0.w;
            As[nb][ac+0][ar+64] = pa1.x; As[nb][ac+1][ar+64] = pa1.y; As[nb][ac+2][ar+64] = pa1.z; As[nb][ac+3][ar+64] = pa1.w;
            *(float4*)&Bs[nb][br][bc] = pb0;
            *(float4*)&Bs[nb][br+8][bc] = pb1;
            __syncthreads();
            buf = nb;
        }
    }

    float4 bj0 = *(const float4*)&bias[col0+n0];
    float4 bj1 = *(const float4*)&bias[col0+n0+4];
#pragma unroll
    for (int i=0;i<8;i++){
        int row = row0 + m0 + i;
        float4 o0, o1;
        o0.x = acc[i][0]+bj0.x; o0.y = acc[i][1]+bj0.y; o0.z = acc[i][2]+bj0.z; o0.w = acc[i][3]+bj0.w;
        o1.x = acc[i][4]+bj1.x; o1.y = acc[i][5]+bj1.y; o1.z = acc[i][6]+bj1.z; o1.w = acc[i][7]+bj1.w;
        *(float4*)&C[(long long)row*NF_ + col0+n0]   = o0;
        *(float4*)&C[(long long)row*NF_ + col0+n0+4] = o1;
    }
}

// ---------------- launch ----------------
extern "C" void kernel_launch(void* const* d_in, const int* in_sizes, int n_in,
                              void* d_out, int out_size)
{
    const float *x, *Wqkv, *bqkv, *Wout, *bout;
    const float *pb_w0, *pb_b0, *pb_w1, *pb_b1, *pb_w2, *pb_b2;

    if (in_sizes[0] == 4194304) {
        x     = (const float*)d_in[0];
        Wqkv  = (const float*)d_in[1];
        bqkv  = (const float*)d_in[2];
        Wout  = (const float*)d_in[3];
        bout  = (const float*)d_in[4];
        pb_w0 = (const float*)d_in[5];
        pb_b0 = (const float*)d_in[6];
        pb_w1 = (const float*)d_in[7];
        pb_b1 = (const float*)d_in[8];
        pb_w2 = (const float*)d_in[9];
        pb_b2 = (const float*)d_in[10];
    } else {
        Wout  = (const float*)d_in[0];
        Wqkv  = (const float*)d_in[1];
        bout  = (const float*)d_in[2];
        bqkv  = (const float*)d_in[3];
        pb_b0 = (const float*)d_in[4];
        pb_b1 = (const float*)d_in[5];
        pb_b2 = (const float*)d_in[6];
        pb_w0 = (const float*)d_in[7];
        pb_w1 = (const float*)d_in[8];
        pb_w2 = (const float*)d_in[9];
        x     = (const float*)d_in[10];
    }
    float* out = (float*)d_out;

    hetero_kernel<<<HET_BLOCKS, 256>>>(x, Wqkv, bqkv,
                                       pb_w0, pb_b0, pb_w1, pb_b1, pb_w2, pb_b2);
    attn_kernel<<<NROWS, 256>>>();
    out_gemm_kernel<<<dim3(NF_/BN, (B_*N_)/BM), 256>>>(Wout, bout, out);
}

// round 11
// speedup vs baseline: 1.1697x; 1.1697x over previous
#include <cuda_runtime.h>
#include <cuda_bf16.h>
#include <stdint.h>

// Problem constants
#define B_   4
#define N_   2048
#define NF_  512
#define H_   8
#define D_   64
#define W_   4
#define NW_  512          // N_/W_
#define KEEP_ 64
#define QKVN 1536         // 3*H*D
#define NROWS (B_*H_*NW_) // 16384
#define BHND (B_*H_*N_*D_)

// SIMT GEMM tiling
#define BM 128
#define BN 128
#define BK 16

typedef unsigned long long u64;

// ---------------- device scratch (no allocations allowed) ----------------
__device__ float g_q[BHND];
__device__ float g_k[BHND];
__device__ float g_v[BHND];
__device__ float g_tab[(2*N_-1)*H_];      // 4095 x 8
__device__ float g_attn[B_*N_*H_*D_];     // (B, N, H*D)

// ---------------- packed fp32x2 helpers (Blackwell fma.rn.f32x2) ----------------
__device__ __forceinline__ u64 pack2(float v){
    u64 r; asm("mov.b64 %0, {%1, %1};" : "=l"(r) : "f"(v)); return r;
}
__device__ __forceinline__ void fma2(u64& c, u64 a, u64 b){
    asm("fma.rn.f32x2 %0, %1, %2, %0;" : "+l"(c) : "l"(a), "l"(b));
}
__device__ __forceinline__ float2 unpack2(u64 v){
    float lo, hi; asm("mov.b64 {%0, %1}, %2;" : "=f"(lo), "=f"(hi) : "l"(v));
    return make_float2(lo, hi);
}

// ---------------- threefry2x32 (JAX-compatible, key=(0,1)) ----------------
__device__ __forceinline__ uint32_t rotl32(uint32_t x, int r){ return (x<<r) | (x>>(32-r)); }

__device__ __forceinline__ void threefry_0_1(uint32_t c0, uint32_t c1, uint32_t& o0, uint32_t& o1){
    const uint32_t ks0 = 0u, ks1 = 1u, ks2 = 0x1BD11BDBu;
    uint32_t x0 = c0 + ks0;
    uint32_t x1 = c1 + ks1;
#define QR(r) { x0 += x1; x1 = rotl32(x1, r); x1 ^= x0; }
    QR(13) QR(15) QR(26) QR(6)   x0 += ks1; x1 += ks2 + 1u;
    QR(17) QR(29) QR(16) QR(24)  x0 += ks2; x1 += ks0 + 2u;
    QR(13) QR(15) QR(26) QR(6)   x0 += ks0; x1 += ks1 + 3u;
    QR(17) QR(29) QR(16) QR(24)  x0 += ks1; x1 += ks2 + 4u;
    QR(13) QR(15) QR(26) QR(6)   x0 += ks2; x1 += ks0 + 5u;
#undef QR
    o0 = x0; o1 = x1;
}

// ---------------- GEMM 1: QKV projection (128x128x16, f32x2 8x8 microtile) ----------------
__global__ __launch_bounds__(256) void qkv_gemm_kernel(const float* __restrict__ A,
                                                       const float* __restrict__ Bm,
                                                       const float* __restrict__ bias)
{
    __shared__ float As[2][BK][BM];
    __shared__ float Bs[2][BK][BN];
    const int tid = threadIdx.x;
    const int row0 = blockIdx.y*BM, col0 = blockIdx.x*BN;

    const int ar = tid>>2;            // 0..63 (+64 for 2nd f4)
    const int ac = (tid&3)*4;
    const int br = tid>>5;            // 0..7 (+8 for 2nd f4)
    const int bc = (tid&31)*4;

    const int wid = tid>>5, lane = tid&31;
    const int m0 = (wid&3)*32 + (lane&3)*8;
    const int n0 = (wid>>2)*64 + (lane>>2)*8;

    // packed accumulators: acc2[i2][j] = rows (m0+2*i2, m0+2*i2+1), col n0+j
    u64 acc2[4][8];
#pragma unroll
    for (int i2=0;i2<4;i2++)
#pragma unroll
        for (int j=0;j<8;j++) acc2[i2][j]=0ull;

    float4 pa0, pa1, pb0, pb1;
    pa0 = *(const float4*)&A[(row0+ar)*NF_ + ac];
    pa1 = *(const float4*)&A[(row0+ar+64)*NF_ + ac];
    pb0 = *(const float4*)&Bm[br*QKVN + col0+bc];
    pb1 = *(const float4*)&Bm[(br+8)*QKVN + col0+bc];
    As[0][ac+0][ar] = pa0.x; As[0][ac+1][ar] = pa0.y; As[0][ac+2][ar] = pa0.z; As[0][ac+3][ar] = pa0.w;
    As[0][ac+0][ar+64] = pa1.x; As[0][ac+1][ar+64] = pa1.y; As[0][ac+2][ar+64] = pa1.z; As[0][ac+3][ar+64] = pa1.w;
    *(float4*)&Bs[0][br][bc] = pb0;
    *(float4*)&Bs[0][br+8][bc] = pb1;
    __syncthreads();

    int buf = 0;
    const int NT = NF_/BK;
    for (int t=0; t<NT; t++){
        const int k0n = (t+1)*BK;
        if (t+1 < NT){
            pa0 = *(const float4*)&A[(row0+ar)*NF_ + k0n+ac];
            pa1 = *(const float4*)&A[(row0+ar+64)*NF_ + k0n+ac];
            pb0 = *(const float4*)&Bm[(k0n+br)*QKVN + col0+bc];
            pb1 = *(const float4*)&Bm[(k0n+br+8)*QKVN + col0+bc];
        }
#pragma unroll
        for (int kk=0; kk<BK; kk++){
            const u64* av = (const u64*)&As[buf][kk][m0];  // 4 u64 = rows m0..m0+7 paired
            u64 a0 = av[0], a1 = av[1], a2 = av[2], a3 = av[3];
            float4 b0 = *(const float4*)&Bs[buf][kk][n0];
            float4 b1 = *(const float4*)&Bs[buf][kk][n0+4];
            float bv[8] = {b0.x,b0.y,b0.z,b0.w,b1.x,b1.y,b1.z,b1.w};
#pragma unroll
            for (int j=0;j<8;j++){
                u64 bb = pack2(bv[j]);
                fma2(acc2[0][j], a0, bb);
                fma2(acc2[1][j], a1, bb);
                fma2(acc2[2][j], a2, bb);
                fma2(acc2[3][j], a3, bb);
            }
        }
        if (t+1 < NT){
            const int nb = buf^1;
            As[nb][ac+0][ar] = pa0.x; As[nb][ac+1][ar] = pa0.y; As[nb][ac+2][ar] = pa0.z; As[nb][ac+3][ar] = pa0.w;
            As[nb][ac+0][ar+64] = pa1.x; As[nb][ac+1][ar+64] = pa1.y; As[nb][ac+2][ar+64] = pa1.z; As[nb][ac+3][ar+64] = pa1.w;
            *(float4*)&Bs[nb][br][bc] = pb0;
            *(float4*)&Bs[nb][br+8][bc] = pb1;
            __syncthreads();
            buf = nb;
        }
    }

    // epilogue: scatter into q/k/v (B,H,N,D)
    float bj[8];
#pragma unroll
    for (int j=0;j<8;j++) bj[j] = bias[col0+n0+j];
#pragma unroll
    for (int i2=0;i2<4;i2++){
        int rowA = row0 + m0 + 2*i2;
        int rowB = rowA + 1;
        int bA = rowA >> 11, nA = rowA & 2047;
        int bB = rowB >> 11, nB = rowB & 2047;
#pragma unroll
        for (int j=0;j<8;j++){
            float2 p = unpack2(acc2[i2][j]);
            int col = col0 + n0 + j;
            int h = col / 192;
            int rem = col - h*192;
            int d = rem / 3;
            int s = rem - d*3;
            float vA = p.x + bj[j];
            float vB = p.y + bj[j];
            long long offA = ((long long)(bA*H_ + h)*N_ + nA)*D_ + d;
            long long offB = ((long long)(bB*H_ + h)*N_ + nB)*D_ + d;
            if (s == 0){ g_q[offA] = vA; g_q[offB] = vB; }
            else if (s == 1){ g_k[offA] = vA; g_k[offB] = vB; }
            else { g_v[offA] = vA; g_v[offB] = vB; }
        }
    }
}

// ---------------- GEMM 2: output projection (128x128x16, f32x2 8x8 microtile) ----------------
__global__ __launch_bounds__(256) void out_gemm_kernel(const float* __restrict__ Bm,
                                                       const float* __restrict__ bias,
                                                       float* __restrict__ C)
{
    __shared__ float As[2][BK][BM];
    __shared__ float Bs[2][BK][BN];
    const int tid = threadIdx.x;
    const int row0 = blockIdx.y*BM, col0 = blockIdx.x*BN;

    const int ar = tid>>2;
    const int ac = (tid&3)*4;
    const int br = tid>>5;
    const int bc = (tid&31)*4;

    const int wid = tid>>5, lane = tid&31;
    const int m0 = (wid&3)*32 + (lane&3)*8;
    const int n0 = (wid>>2)*64 + (lane>>2)*8;

    u64 acc2[4][8];
#pragma unroll
    for (int i2=0;i2<4;i2++)
#pragma unroll
        for (int j=0;j<8;j++) acc2[i2][j]=0ull;

    float4 pa0, pa1, pb0, pb1;
    pa0 = *(const float4*)&g_attn[(row0+ar)*NF_ + ac];
    pa1 = *(const float4*)&g_attn[(row0+ar+64)*NF_ + ac];
    pb0 = *(const float4*)&Bm[br*NF_ + col0+bc];
    pb1 = *(const float4*)&Bm[(br+8)*NF_ + col0+bc];
    As[0][ac+0][ar] = pa0.x; As[0][ac+1][ar] = pa0.y; As[0][ac+2][ar] = pa0.z; As[0][ac+3][ar] = pa0.w;
    As[0][ac+0][ar+64] = pa1.x; As[0][ac+1][ar+64] = pa1.y; As[0][ac+2][ar+64] = pa1.z; As[0][ac+3][ar+64] = pa1.w;
    *(float4*)&Bs[0][br][bc] = pb0;
    *(float4*)&Bs[0][br+8][bc] = pb1;
    __syncthreads();

    int buf = 0;
    const int NT = NF_/BK;
    for (int t=0; t<NT; t++){
        const int k0n = (t+1)*BK;
        if (t+1 < NT){
            pa0 = *(const float4*)&g_attn[(row0+ar)*NF_ + k0n+ac];
            pa1 = *(const float4*)&g_attn[(row0+ar+64)*NF_ + k0n+ac];
            pb0 = *(const float4*)&Bm[(k0n+br)*NF_ + col0+bc];
            pb1 = *(const float4*)&Bm[(k0n+br+8)*NF_ + col0+bc];
        }
#pragma unroll
        for (int kk=0; kk<BK; kk++){
            const u64* av = (const u64*)&As[buf][kk][m0];
            u64 a0 = av[0], a1 = av[1], a2 = av[2], a3 = av[3];
            float4 b0 = *(const float4*)&Bs[buf][kk][n0];
            float4 b1 = *(const float4*)&Bs[buf][kk][n0+4];
            float bv[8] = {b0.x,b0.y,b0.z,b0.w,b1.x,b1.y,b1.z,b1.w};
#pragma unroll
            for (int j=0;j<8;j++){
                u64 bb = pack2(bv[j]);
                fma2(acc2[0][j], a0, bb);
                fma2(acc2[1][j], a1, bb);
                fma2(acc2[2][j], a2, bb);
                fma2(acc2[3][j], a3, bb);
            }
        }
        if (t+1 < NT){
            const int nb = buf^1;
            As[nb][ac+0][ar] = pa0.x; As[nb][ac+1][ar] = pa0.y; As[nb][ac+2][ar] = pa0.z; As[nb][ac+3][ar] = pa0.w;
            As[nb][ac+0][ar+64] = pa1.x; As[nb][ac+1][ar+64] = pa1.y; As[nb][ac+2][ar+64] = pa1.z; As[nb][ac+3][ar+64] = pa1.w;
            *(float4*)&Bs[nb][br][bc] = pb0;
            *(float4*)&Bs[nb][br+8][bc] = pb1;
            __syncthreads();
            buf = nb;
        }
    }

    float4 bj0 = *(const float4*)&bias[col0+n0];
    float4 bj1 = *(const float4*)&bias[col0+n0+4];
    float bj[8] = {bj0.x,bj0.y,bj0.z,bj0.w,bj1.x,bj1.y,bj1.z,bj1.w};
#pragma unroll
    for (int i2=0;i2<4;i2++){
        int rowA = row0 + m0 + 2*i2;
        float oA[8], oB[8];
#pragma unroll
        for (int j=0;j<8;j++){
            float2 p = unpack2(acc2[i2][j]);
            oA[j] = p.x + bj[j];
            oB[j] = p.y + bj[j];
        }
        *(float4*)&C[(long long)rowA*NF_ + col0+n0]       = make_float4(oA[0],oA[1],oA[2],oA[3]);
        *(float4*)&C[(long long)rowA*NF_ + col0+n0+4]     = make_float4(oA[4],oA[5],oA[6],oA[7]);
        *(float4*)&C[(long long)(rowA+1)*NF_ + col0+n0]   = make_float4(oB[0],oB[1],oB[2],oB[3]);
        *(float4*)&C[(long long)(rowA+1)*NF_ + col0+n0+4] = make_float4(oB[4],oB[5],oB[6],oB[7]);
    }
}

// ---------------- Position-bias MLP: table (4095, 8) ----------------
__global__ void pb_kernel(const float* __restrict__ w0, const float* __restrict__ b0,
                          const float* __restrict__ w1, const float* __restrict__ b1,
                          const float* __restrict__ w2, const float* __restrict__ b2)
{
    __shared__ float h0[16*512];
    int tid = threadIdx.x;
    int r0 = blockIdx.x * 16;

    for (int i = tid; i < 16*512; i += 256){
        int r = i >> 9, j = i & 511;
        int rr = r0 + r;
        float v = 0.f;
        if (rr < 2*N_-1){
            float pos = (float)(rr - (N_-1));
            float t = pos * w0[j] + b0[j];
            v = t / (1.f + expf(-t));
        }
        h0[r*512 + j] = v;
    }
    __syncthreads();

    float acc[2][16];
#pragma unroll
    for (int c=0;c<2;c++)
#pragma unroll
        for (int r=0;r<16;r++) acc[c][r]=0.f;

    for (int k=0;k<512;k++){
        float wA = w1[k*512 + tid];
        float wB = w1[k*512 + tid + 256];
#pragma unroll
        for (int r=0;r<16;r++){
            float hv = h0[r*512 + k];
            acc[0][r] += hv*wA;
            acc[1][r] += hv*wB;
        }
    }
    __syncthreads();

#pragma unroll
    for (int c=0;c<2;c++){
        int j = tid + c*256;
        float bb = b1[j];
#pragma unroll
        for (int r=0;r<16;r++){
            float t = acc[c][r] + bb;
            h0[r*512 + j] = t / (1.f + expf(-t));
        }
    }
    __syncthreads();

    int warp = tid >> 5, lane = tid & 31;
    for (int task = warp; task < 128; task += 8){
        int r = task >> 3, o = task & 7;
        float s = 0.f;
        for (int k = lane; k < 512; k += 32) s += h0[r*512 + k] * w2[k*8 + o];
#pragma unroll
        for (int off=16; off; off>>=1) s += __shfl_xor_sync(0xffffffffu, s, off);
        if (lane == 0){
            int rr = r0 + r;
            if (rr < 2*N_-1) g_tab[rr*8 + o] = s + b2[o];
        }
    }
}

// ---------------- fast block exclusive scan (256 threads) ----------------
__device__ __forceinline__ int block_scan_excl(int val, int tid, int* scratch){
    int lane = tid & 31, wid = tid >> 5;
    int x = val;
#pragma unroll
    for (int o=1; o<32; o<<=1){
        int t = __shfl_up_sync(0xffffffffu, x, o);
        if (lane >= o) x += t;
    }
    if (lane == 31) scratch[wid] = x;
    __syncthreads();
    if (wid == 0 && lane < 8){
        int y = scratch[lane];
#pragma unroll
        for (int o=1; o<8; o<<=1){
            int t = __shfl_up_sync(0xFFu, y, o);
            if (lane >= o) y += t;
        }
        scratch[lane] = y;
    }
    __syncthreads();
    int base = (wid == 0) ? 0 : scratch[wid-1];
    return base + x - val;
}

// ---------------- fused top-k + attention per (b,h,blk) ----------------
__global__ __launch_bounds__(256) void topk_attn_kernel()
{
    __shared__ float qs[4*64];
    __shared__ float ks[64*68];     // topk phase: first 264 ints = hist[256] + scratch[8]
    __shared__ float vs[64*68];
    __shared__ float sv[4*64];
    __shared__ float pm[4], psum[4];
    __shared__ int sidx[64];
    __shared__ unsigned s_prefix;
    __shared__ int s_target;

    int row = blockIdx.x, tid = threadIdx.x;
    int w = row & (NW_-1);
    int bh = row >> 9;
    int h = bh & 7, b = bh >> 3;

    int* hist    = (int*)ks;
    int* scratch = ((int*)ks) + 256;

    const float* qbase = g_q + ((long long)bh * N_ + w*W_) * D_;
    float qreg = qbase[tid];

    unsigned kk[8];
    unsigned base = (unsigned)row * 2048u;
#pragma unroll
    for (int q=0; q<8; q++){
        int n = tid*8 + q;
        unsigned i = base + (unsigned)n;
        unsigned o0, o1;
        threefry_0_1(0u, i, o0, o1);
        unsigned bits = o0 ^ o1;
        float u = __uint_as_float((bits >> 9) | 0x3F800000u) - 1.0f;
        float noise = 3.0f * expf(-0.5f * log1pf(-u));
        int jblk = n >> 2;
        int dd = w - jblk; if (dd < 0) dd = -dd;
        float score = (float)dd - noise;
        unsigned fb = __float_as_uint(score);
        kk[q] = (fb & 0x80000000u) ? ~fb : (fb | 0x80000000u);
    }

    unsigned prefix = 0, mask = 0;
    int target = KEEP_;
#pragma unroll 1
    for (int pass = 0; pass < 4; pass++){
        int shift = 24 - 8*pass;
        hist[tid] = 0;
        __syncthreads();
#pragma unroll
        for (int q=0; q<8; q++){
            if ((kk[q] & mask) == prefix) atomicAdd(&hist[(kk[q] >> shift) & 255u], 1);
        }
        __syncthreads();
        int hv = hist[tid];
        __syncthreads();
        int excl = block_scan_excl(hv, tid, scratch);
        int incl = excl + hv;
        if (excl < target && target <= incl){
            s_prefix = prefix | ((unsigned)tid << shift);
            s_target = target - excl;
        }
        __syncthreads();
        prefix = s_prefix; target = s_target;
        mask |= (0xFFu << shift);
    }
    unsigned T = prefix;
    int r = target;

    int eq_cnt = 0;
#pragma unroll
    for (int q=0;q<8;q++) eq_cnt += (kk[q] == T);
    int eq_off = block_scan_excl(eq_cnt, tid, scratch);

    unsigned chflag = 0; int ch_cnt = 0; int er = eq_off;
#pragma unroll
    for (int q=0;q<8;q++){
        unsigned k = kk[q];
        bool ch = false;
        if (k < T) ch = true;
        else if (k == T){ ch = (er < r); er++; }
        if (ch){ chflag |= (1u<<q); ch_cnt++; }
    }
    int pos = block_scan_excl(ch_cnt, tid, scratch);
#pragma unroll
    for (int q=0;q<8;q++){
        if (chflag & (1u<<q)){
            sidx[pos] = tid*8 + q;
            pos++;
        }
    }
    __syncthreads();

    // ---- attention phase ----
    const float4* kb4 = (const float4*)(g_k + (long long)bh * N_ * D_);
    const float4* vb4 = (const float4*)(g_v + (long long)bh * N_ * D_);

    qs[tid] = qreg;
    for (int i = tid; i < 64*16; i += 256){
        int z = i >> 4, d4 = i & 15;
        int key = sidx[z];
        *(float4*)&ks[z*68 + d4*4] = kb4[key*16 + d4];
        *(float4*)&vs[z*68 + d4*4] = vb4[key*16 + d4];
    }
    __syncthreads();

    int wi = tid >> 6, z = tid & 63;
    const float4* qs4 = (const float4*)qs;
    const float4* ks4 = (const float4*)ks;
    float acc = 0.f;
#pragma unroll
    for (int d4=0; d4<16; d4++){
        float4 qv = qs4[wi*16 + d4];
        float4 kv = ks4[z*17 + d4];
        acc += qv.x*kv.x + qv.y*kv.y + qv.z*kv.z + qv.w*kv.w;
    }
    int rel = (w*W_ + wi) - sidx[z] + (N_-1);
    float val = acc * 0.125f + g_tab[rel*8 + h];
    sv[tid] = val;
    __syncthreads();

    if (tid < 128){
        int wr = tid >> 5, lane = tid & 31;
        float v1 = sv[wr*64 + lane], v2 = sv[wr*64 + lane + 32];
        float m = fmaxf(v1, v2);
#pragma unroll
        for (int off=16; off; off>>=1) m = fmaxf(m, __shfl_xor_sync(0xffffffffu, m, off));
        float s = expf(v1 - m) + expf(v2 - m);
#pragma unroll
        for (int off=16; off; off>>=1) s += __shfl_xor_sync(0xffffffffu, s, off);
        if (lane == 0){ pm[wr] = m; psum[wr] = s; }
    }
    __syncthreads();

    float p = expf(val - pm[wi]) / psum[wi];
    sv[tid] = p;
    __syncthreads();

    int d = z;
    const float4* sv4 = (const float4*)sv;
    float o = 0.f;
#pragma unroll
    for (int z4=0; z4<16; z4++){
        float4 p4 = sv4[wi*16 + z4];
        o += p4.x*vs[(z4*4+0)*68 + d] + p4.y*vs[(z4*4+1)*68 + d]
           + p4.z*vs[(z4*4+2)*68 + d] + p4.w*vs[(z4*4+3)*68 + d];
    }
    g_attn[(((long long)b*N_ + w*W_ + wi)*H_ + h)*D_ + d] = o;
}

// ---------------- launch ----------------
extern "C" void kernel_launch(void* const* d_in, const int* in_sizes, int n_in,
                              void* d_out, int out_size)
{
    const float *x, *Wqkv, *bqkv, *Wout, *bout;
    const float *pb_w0, *pb_b0, *pb_w1, *pb_b1, *pb_w2, *pb_b2;

    if (in_sizes[0] == 4194304) {
        x     = (const float*)d_in[0];
        Wqkv  = (const float*)d_in[1];
        bqkv  = (const float*)d_in[2];
        Wout  = (const float*)d_in[3];
        bout  = (const float*)d_in[4];
        pb_w0 = (const float*)d_in[5];
        pb_b0 = (const float*)d_in[6];
        pb_w1 = (const float*)d_in[7];
        pb_b1 = (const float*)d_in[8];
        pb_w2 = (const float*)d_in[9];
        pb_b2 = (const float*)d_in[10];
    } else {
        Wout  = (const float*)d_in[0];
        Wqkv  = (const float*)d_in[1];
        bout  = (const float*)d_in[2];
        bqkv  = (const float*)d_in[3];
        pb_b0 = (const float*)d_in[4];
        pb_b1 = (const float*)d_in[5];
        pb_b2 = (const float*)d_in[6];
        pb_w0 = (const float*)d_in[7];
        pb_w1 = (const float*)d_in[8];
        pb_w2 = (const float*)d_in[9];
        x     = (const float*)d_in[10];
    }
    float* out = (float*)d_out;

    qkv_gemm_kernel<<<dim3(QKVN/BN, (B_*N_)/BM), 256>>>(x, Wqkv, bqkv);
    pb_kernel<<<256, 256>>>(pb_w0, pb_b0, pb_w1, pb_b1, pb_w2, pb_b2);
    topk_attn_kernel<<<NROWS, 256>>>();
    out_gemm_kernel<<<dim3(NF_/BN, (B_*N_)/BM), 256>>>(Wout, bout, out);
}